// round 5
// baseline (speedup 1.0000x reference)
#include <cuda_runtime.h>
#include <math.h>

#define Bc   2
#define HIDc 128
#define NVc  16
#define Hh   361
#define Ww   720
#define HW   (Hh*Ww)          // 259920
#define NPIX (Bc*HW)          // 519840
#define Hp   (Hh+4)           // 365
#define Wp   (Ww+4)           // 724

// scratch (static device globals -- no allocation)
__device__ float g_proj[Bc*NVc*HW];   // down-projected velocities [B*NV, H, W]
__device__ float g_y[Bc*NVc*HW];      // interpolated + depthwise-scaled [B*NV, H, W]

// ---------------- packed f32x2 helpers (FFMA2) ----------------
static __device__ __forceinline__ unsigned long long pk2(float x, float y) {
    unsigned long long r;
    asm("mov.b64 %0, {%1, %2};" : "=l"(r) : "f"(x), "f"(y));
    return r;
}
static __device__ __forceinline__ void upk2(unsigned long long r, float& x, float& y) {
    asm("mov.b64 {%0, %1}, %2;" : "=f"(x), "=f"(y) : "l"(r));
}
static __device__ __forceinline__ unsigned long long ffma2(unsigned long long a,
                                                           unsigned long long b,
                                                           unsigned long long c) {
    unsigned long long d;
    asm("fma.rn.f32x2 %0, %1, %2, %3;" : "=l"(d) : "l"(a), "l"(b), "l"(c));
    return d;
}

// ---------------- K1: down projection (hidden[B,128,H,W] -> g_proj[B,16,H,W]) ----------------
// 2 pixels per thread: acc[v] = (px0,px1) packed. Lower register pressure than
// the 4px variant (R3 profile: occupancy-limited), same FFMA2 per pixel.
__global__ void __launch_bounds__(256) k_down(const float* __restrict__ x,
                                              const float* __restrict__ dw,
                                              const float* __restrict__ db) {
    __shared__ __align__(16) unsigned long long wsh[HIDc*NVc];  // [c][v], (w,w) pairs
    int tid = threadIdx.x;
    for (int i = tid; i < HIDc*NVc; i += 256) {
        int c = i >> 4, v = i & 15;
        float w = dw[v*HIDc + c];
        wsh[i] = pk2(w, w);
    }
    __syncthreads();

    int t = blockIdx.x*256 + tid;         // pixel-pair id
    int q0 = t * 2;
    if (q0 >= NPIX) return;
    int b = q0 / HW;
    int p = q0 - b*HW;                    // HW even -> pair never crosses b

    const float* xb = x + (size_t)b*HIDc*HW + p;

    unsigned long long acc[NVc];
    #pragma unroll
    for (int v = 0; v < NVc; v++) {
        float bb = db[v];
        acc[v] = pk2(bb, bb);
    }

    #pragma unroll 4
    for (int c = 0; c < HIDc; c++) {
        float2 xv = *(const float2*)(xb + (size_t)c*HW);
        unsigned long long xp = pk2(xv.x, xv.y);
        const ulonglong2* wr = (const ulonglong2*)&wsh[c*NVc];
        #pragma unroll
        for (int j = 0; j < 8; j++) {
            ulonglong2 ww = wr[j];
            acc[2*j]   = ffma2(xp, ww.x, acc[2*j]);
            acc[2*j+1] = ffma2(xp, ww.y, acc[2*j+1]);
        }
    }

    float* pb = g_proj + (size_t)b*NVc*HW + p;
    #pragma unroll
    for (int v = 0; v < NVc; v++) {
        float2 r;
        upk2(acc[v], r.x, r.y);
        *(float2*)(pb + (size_t)v*HW) = r;
    }
}

// ---------------- pole fix (rows 0 and H-1 -> longitude mean) ----------------
__global__ void __launch_bounds__(256) k_pole(float* pext, int use_proj) {
    float* base = use_proj ? g_proj : pext;
    int c   = blockIdx.x >> 1;
    int row = (blockIdx.x & 1) ? (Hh - 1) : 0;
    float* rp = base + ((size_t)c*Hh + row)*Ww;

    __shared__ float sh[256];
    float s = 0.0f;
    for (int i = threadIdx.x; i < Ww; i += 256) s += rp[i];
    sh[threadIdx.x] = s;
    __syncthreads();
    for (int o = 128; o > 0; o >>= 1) {
        if (threadIdx.x < o) sh[threadIdx.x] += sh[threadIdx.x + o];
        __syncthreads();
    }
    float m = sh[0] / (float)Ww;
    for (int i = threadIdx.x; i < Ww; i += 256) rp[i] = m;
}

// ---------------- K2: advect (departure + geo-padded bicubic + depthwise) ----------------
// One thread per (b, pixel); loops over the 16 velocity channels. Shares
// sincos(lat_g) and all grid constants across the 16 channels (16x fewer
// grid-trig ops than one-thread-per-sample). All per-channel u/v/tap/y
// accesses remain coalesced across the warp.
__global__ void __launch_bounds__(256) k_advect(const float* __restrict__ uin,
                                                const float* __restrict__ vin,
                                                const float* __restrict__ dtp,
                                                const float* __restrict__ latg,
                                                const float* __restrict__ lonG,
                                                const float* __restrict__ dww,
                                                const float* __restrict__ dwb) {
    int t = blockIdx.x*256 + threadIdx.x;
    if (t >= NPIX) return;
    int b = t / HW;
    int p = t - b*HW;

    float dt = __ldg(dtp);
    float lat_g = __ldg(&latg[p]);
    float lon_g = __ldg(&lonG[p]);
    float min_lat = __ldg(&latg[0]);
    float max_lat = __ldg(&latg[(Hh-1)*Ww]);
    float min_lon = __ldg(&lonG[0]);
    float max_lon = __ldg(&lonG[Ww-1]);
    float inv_dlat = (float)(Hh - 1) / (max_lat - min_lat);
    float inv_dlon = (float)(Ww - 1) / (max_lon - min_lon);

    float slg, clg;
    __sincosf(lat_g, &slg, &clg);
    const float TWO_PI = 6.28318530717958647692f;

    const float* ubase = uin + (size_t)b*NVc*HW + p;
    const float* vbase = vin + (size_t)b*NVc*HW + p;
    const float* prb   = g_proj + (size_t)b*NVc*HW;
    float*       yb    = g_y    + (size_t)b*NVc*HW + p;

    #pragma unroll 1
    for (int v = 0; v < NVc; v++) {
        float uu = ubase[(size_t)v*HW];
        float vv = vbase[(size_t)v*HW];

        float lon_pr = -uu * dt;
        float lat_pr = -vv * dt;
        float slp, clp, slo, clo;
        __sincosf(lat_pr, &slp, &clp);
        __sincosf(lon_pr, &slo, &clo);

        float sin_lat = slp*clg + clp*clo*slg;
        const float CL = 1.0f - 1e-7f;
        sin_lat = fminf(fmaxf(sin_lat, -CL), CL);
        float lat_dep = asinf(sin_lat);

        float num = clp * slo;
        float den = clp*clo*clg - slp*slg;
        float lon_dep = lon_g + atan2f(num, den) + TWO_PI;  // in [pi, 5*pi)
        if (lon_dep >= TWO_PI) lon_dep -= TWO_PI;
        if (lon_dep >= TWO_PI) lon_dep -= TWO_PI;

        float pix_x = (lon_dep - min_lon) * inv_dlon;
        float pix_y = (lat_dep - min_lat) * inv_dlat;
        // normalize/unnormalize round trip (align_corners=True), fp32-faithful
        float gx = 2.0f * ((pix_x + 2.0f) / (float)(Wp - 1)) - 1.0f;
        float gy = 2.0f * ((pix_y + 2.0f) / (float)(Hp - 1)) - 1.0f;
        float ix = (gx + 1.0f) * 0.5f * (float)(Wp - 1);
        float iy = (gy + 1.0f) * 0.5f * (float)(Hp - 1);

        float xf = floorf(ix), yf = floorf(iy);
        float tx = ix - xf,    ty = iy - yf;
        int x0 = (int)xf, y0 = (int)yf;
        x0 = min(max(x0, 1), Ww + 1);     // safety clamp (no-op normally)
        y0 = min(max(y0, 1), Hh + 1);

        const float Aa = -0.75f;
        float t1 = tx + 1.0f, t2 = 1.0f - tx, t3 = 2.0f - tx;
        float wx0 = ((Aa*t1 - 5.0f*Aa)*t1 + 8.0f*Aa)*t1 - 4.0f*Aa;
        float wx1 = ((Aa + 2.0f)*tx - (Aa + 3.0f))*tx*tx + 1.0f;
        float wx2 = ((Aa + 2.0f)*t2 - (Aa + 3.0f))*t2*t2 + 1.0f;
        float wx3 = ((Aa*t3 - 5.0f*Aa)*t3 + 8.0f*Aa)*t3 - 4.0f*Aa;
        float s1 = ty + 1.0f, s2 = 1.0f - ty, s3 = 2.0f - ty;
        float wy0 = ((Aa*s1 - 5.0f*Aa)*s1 + 8.0f*Aa)*s1 - 4.0f*Aa;
        float wy1 = ((Aa + 2.0f)*ty - (Aa + 3.0f))*ty*ty + 1.0f;
        float wy2 = ((Aa + 2.0f)*s2 - (Aa + 3.0f))*s2*s2 + 1.0f;
        float wy3 = ((Aa*s3 - 5.0f*Aa)*s3 + 8.0f*Aa)*s3 - 4.0f*Aa;

        // column indices: cyclic (unshifted) and pole-shifted (+W/2)
        int cbase = x0 - 3;
        int cb0 = cbase;     if (cb0 <  0)  cb0 += Ww; if (cb0 >= Ww) cb0 -= Ww;
        int cb1 = cbase + 1; if (cb1 <  0)  cb1 += Ww; if (cb1 >= Ww) cb1 -= Ww;
        int cb2 = cbase + 2; if (cb2 <  0)  cb2 += Ww; if (cb2 >= Ww) cb2 -= Ww;
        int cb3 = cbase + 3; if (cb3 <  0)  cb3 += Ww; if (cb3 >= Ww) cb3 -= Ww;
        int cs0 = cb0 + Ww/2; if (cs0 >= Ww) cs0 -= Ww;
        int cs1 = cb1 + Ww/2; if (cs1 >= Ww) cs1 -= Ww;
        int cs2 = cb2 + Ww/2; if (cs2 >= Ww) cs2 -= Ww;
        int cs3 = cb3 + Ww/2; if (cs3 >= Ww) cs3 -= Ww;

        const float* pr = prb + (size_t)v*HW;
        float acc = 0.0f;

#define ROWSUM(WYV, DY) do {                                                   \
            int yy = y0 - 1 + (DY);                                            \
            int yi = yy - 2;                                                   \
            int r, shf;                                                        \
            if (yi < 0)        { r = 1 - yy;        shf = 1; }                 \
            else if (yi >= Hh) { r = 2*Hh + 1 - yy; shf = 1; }                 \
            else               { r = yi;            shf = 0; }                 \
            const float* row = pr + (size_t)r*Ww;                              \
            int c0 = shf ? cs0 : cb0;                                          \
            int c1 = shf ? cs1 : cb1;                                          \
            int c2 = shf ? cs2 : cb2;                                          \
            int c3 = shf ? cs3 : cb3;                                          \
            float s = fmaf(wx3, __ldg(&row[c3]),                               \
                      fmaf(wx2, __ldg(&row[c2]),                               \
                      fmaf(wx1, __ldg(&row[c1]), wx0*__ldg(&row[c0]))));       \
            acc = fmaf((WYV), s, acc);                                         \
        } while (0)

        ROWSUM(wy0, 0);
        ROWSUM(wy1, 1);
        ROWSUM(wy2, 2);
        ROWSUM(wy3, 3);
#undef ROWSUM

        yb[(size_t)v*HW] = acc * __ldg(&dww[v]) + __ldg(&dwb[v]);
    }
}

// ---------------- K3: up projection (g_y[B,16,H,W] -> out[B,128,H,W]) ----------------
// 2 pixels per thread: y pairs in 16 u64 regs, streaming accumulator per o.
__global__ void __launch_bounds__(256) k_up(const float* __restrict__ uw,
                                            const float* __restrict__ ub,
                                            float* __restrict__ out) {
    __shared__ __align__(16) unsigned long long wsh[HIDc*NVc];  // [o][v], (w,w) pairs
    __shared__ float bsh[HIDc];
    int tid = threadIdx.x;
    for (int i = tid; i < HIDc*NVc; i += 256) {
        float w = uw[i];                  // up_w row-major [o][v]
        wsh[i] = pk2(w, w);
    }
    if (tid < HIDc) bsh[tid] = ub[tid];
    __syncthreads();

    int t = blockIdx.x*256 + tid;         // pixel-pair id
    int q0 = t * 2;
    if (q0 >= NPIX) return;
    int b = q0 / HW;
    int p = q0 - b*HW;

    const float* yb = g_y + (size_t)b*NVc*HW + p;
    unsigned long long yp[NVc];
    #pragma unroll
    for (int v = 0; v < NVc; v++) {
        float2 yv = *(const float2*)(yb + (size_t)v*HW);
        yp[v] = pk2(yv.x, yv.y);
    }

    float* ob = out + (size_t)b*HIDc*HW + p;
    #pragma unroll 4
    for (int o = 0; o < HIDc; o++) {
        float bias = bsh[o];
        unsigned long long a = pk2(bias, bias);
        const ulonglong2* wr = (const ulonglong2*)&wsh[o*NVc];
        #pragma unroll
        for (int j = 0; j < 8; j++) {
            ulonglong2 ww = wr[j];
            a = ffma2(yp[2*j],   ww.x, a);
            a = ffma2(yp[2*j+1], ww.y, a);
        }
        float2 r;
        upk2(a, r.x, r.y);
        *(float2*)(ob + (size_t)o*HW) = r;
    }
}

// ---------------- launcher ----------------
extern "C" void kernel_launch(void* const* d_in, const int* in_sizes, int n_in,
                              void* d_out, int out_size) {
    const float* hidden = (const float*)d_in[0];
    const float* u      = (const float*)d_in[1];
    const float* v      = (const float*)d_in[2];
    const float* dt     = (const float*)d_in[3];
    const float* latg   = (const float*)d_in[4];
    const float* lonG   = (const float*)d_in[5];
    const float* down_w = (const float*)d_in[6];
    const float* down_b = (const float*)d_in[7];
    const float* dw_w   = (const float*)d_in[8];
    const float* dw_b   = (const float*)d_in[9];
    const float* up_w   = (const float*)d_in[10];
    const float* up_b   = (const float*)d_in[11];
    float* out = (float*)d_out;

    int pair_blocks = (NPIX/2 + 255) / 256;                   // 1016
    k_down<<<pair_blocks, 256>>>(hidden, down_w, down_b);
    k_pole<<<Bc*NVc*2, 256>>>(nullptr, 1);                    // fix g_proj poles
    k_advect<<<(NPIX + 255)/256, 256>>>(u, v, dt, latg, lonG, dw_w, dw_b);
    k_up<<<pair_blocks, 256>>>(up_w, up_b, out);
    k_pole<<<Bc*HIDc*2, 256>>>(out, 0);                       // fix output poles
}

// round 7
// speedup vs baseline: 1.3188x; 1.3188x over previous
#include <cuda_runtime.h>
#include <math.h>

#define Bc   2
#define HIDc 128
#define NVc  16
#define Hh   361
#define Ww   720
#define HW   (Hh*Ww)          // 259920
#define NPIX (Bc*HW)          // 519840
#define NSAMP (Bc*NVc*HW)     // 8,317,440

// scratch (static device globals -- no allocation)
__device__ float g_proj[Bc*NVc*HW];   // down-projected velocities [B*NV, H, W]
__device__ float g_y[Bc*NVc*HW];      // interpolated + depthwise-scaled [B*NV, H, W]
__device__ float g_rowtrig[Hh*2];     // per-row sin(lat), cos(lat)
__device__ float g_consts[8];         // dt, min_lat, min_lon, inv_dlat, inv_dlon

// ---------------- packed f32x2 helpers (FFMA2) ----------------
static __device__ __forceinline__ unsigned long long pk2(float x, float y) {
    unsigned long long r;
    asm("mov.b64 %0, {%1, %2};" : "=l"(r) : "f"(x), "f"(y));
    return r;
}
static __device__ __forceinline__ void upk2(unsigned long long r, float& x, float& y) {
    asm("mov.b64 {%0, %1}, %2;" : "=f"(x), "=f"(y) : "l"(r));
}
static __device__ __forceinline__ unsigned long long ffma2(unsigned long long a,
                                                           unsigned long long b,
                                                           unsigned long long c) {
    unsigned long long d;
    asm("fma.rn.f32x2 %0, %1, %2, %3;" : "=l"(d) : "l"(a), "l"(b), "l"(c));
    return d;
}
static __device__ __forceinline__ float rcp_fast(float x) {
    float r; asm("rcp.approx.f32 %0, %1;" : "=f"(r) : "f"(x)); return r;
}
static __device__ __forceinline__ float rsqrt_fast(float x) {
    float r; asm("rsqrt.approx.f32 %0, %1;" : "=f"(r) : "f"(x)); return r;
}

// fast asin: A&S 4.4.46 degree-7, |err| ~ 2e-8 rad
static __device__ __forceinline__ float asin_fast(float x) {
    float s = fabsf(x);
    float p = fmaf(s, -0.0012624911f, 0.0066700901f);
    p = fmaf(p, s, -0.0170881256f);
    p = fmaf(p, s,  0.0308918810f);
    p = fmaf(p, s, -0.0501743046f);
    p = fmaf(p, s,  0.0889789874f);
    p = fmaf(p, s, -0.2145988016f);
    p = fmaf(p, s,  1.5707963050f);
    float q  = 1.0f - s;
    float sq = q * rsqrt_fast(fmaxf(q, 1e-30f));   // sqrt(1-s), q >= ~6e-8 by clamp
    float r  = 1.5707963267948966f - sq * p;        // asin(|x|)
    return copysignf(r, x);
}

// fast atan2: ratio of min/max + odd minimax poly on [0,1] (~1e-7 rad) + quadrant fix
static __device__ __forceinline__ float atan2_fast(float y, float x) {
    const float PI_F  = 3.14159265358979323846f;
    const float PI_2F = 1.57079632679489661923f;
    float ax = fabsf(x), ay = fabsf(y);
    float mx = fmaxf(ax, ay), mn = fminf(ax, ay);
    float t  = mn * rcp_fast(fmaxf(mx, 1e-30f));    // in [0,1]
    float r  = t * t;
    float p = fmaf(r, -0.0040540580f, 0.0218612288f);
    p = fmaf(p, r, -0.0559098861f);
    p = fmaf(p, r,  0.0964200441f);
    p = fmaf(p, r, -0.1390853351f);
    p = fmaf(p, r,  0.1994653599f);
    p = fmaf(p, r, -0.3332985605f);
    p = fmaf(p, r,  0.9999993329f);
    float a = t * p;                                 // atan(mn/mx)
    if (ay > ax) a = PI_2F - a;
    if (x < 0.0f) a = PI_F - a;
    return copysignf(a, y);
}

// ---------------- K0: precompute row trig + scalar constants ----------------
__global__ void k_prep(const float* __restrict__ latg,
                       const float* __restrict__ lonG,
                       const float* __restrict__ dtp) {
    int t = blockIdx.x*256 + threadIdx.x;
    if (t < Hh) {
        float lg = latg[(size_t)t*Ww];
        g_rowtrig[2*t]   = sinf(lg);   // accurate; only 361 calls
        g_rowtrig[2*t+1] = cosf(lg);
    }
    if (t == Hh) {
        float min_lat = latg[0], max_lat = latg[(size_t)(Hh-1)*Ww];
        float min_lon = lonG[0], max_lon = lonG[Ww-1];
        g_consts[0] = *dtp;
        g_consts[1] = min_lat;
        g_consts[2] = min_lon;
        g_consts[3] = (float)(Hh-1) / (max_lat - min_lat);
        g_consts[4] = (float)(Ww-1) / (max_lon - min_lon);
    }
}

// ---------------- K1: down projection (hidden[B,128,H,W] -> g_proj[B,16,H,W]) ----------------
// 4 pixels/thread, FFMA2, float4 I/O (R2 config: L1/LSU-optimal width).
__global__ void __launch_bounds__(256) k_down(const float* __restrict__ x,
                                              const float* __restrict__ dw,
                                              const float* __restrict__ db) {
    __shared__ __align__(16) unsigned long long wsh[HIDc*NVc];  // [c][v], (w,w) pairs
    int tid = threadIdx.x;
    for (int i = tid; i < HIDc*NVc; i += 256) {
        int c = i >> 4, v = i & 15;
        float w = dw[v*HIDc + c];
        wsh[i] = pk2(w, w);
    }
    __syncthreads();

    int t = blockIdx.x*256 + tid;         // pixel-quad id
    int q0 = t * 4;
    if (q0 >= NPIX) return;
    int b = q0 / HW;
    int p = q0 - b*HW;                    // HW % 4 == 0 -> quad never crosses b

    const float* xb = x + (size_t)b*HIDc*HW + p;

    unsigned long long acc[NVc*2];        // acc[2v]=(px0,px1), acc[2v+1]=(px2,px3)
    #pragma unroll
    for (int v = 0; v < NVc; v++) {
        float bb = db[v];
        acc[2*v]   = pk2(bb, bb);
        acc[2*v+1] = acc[2*v];
    }

    #pragma unroll 4
    for (int c = 0; c < HIDc; c++) {
        float4 xv = *(const float4*)(xb + (size_t)c*HW);
        unsigned long long x0 = pk2(xv.x, xv.y);
        unsigned long long x1 = pk2(xv.z, xv.w);
        const ulonglong2* wr = (const ulonglong2*)&wsh[c*NVc];
        #pragma unroll
        for (int j = 0; j < 8; j++) {
            ulonglong2 ww = wr[j];
            acc[4*j+0] = ffma2(x0, ww.x, acc[4*j+0]);
            acc[4*j+1] = ffma2(x1, ww.x, acc[4*j+1]);
            acc[4*j+2] = ffma2(x0, ww.y, acc[4*j+2]);
            acc[4*j+3] = ffma2(x1, ww.y, acc[4*j+3]);
        }
    }

    float* pb = g_proj + (size_t)b*NVc*HW + p;
    #pragma unroll
    for (int v = 0; v < NVc; v++) {
        float4 r;
        upk2(acc[2*v],   r.x, r.y);
        upk2(acc[2*v+1], r.z, r.w);
        *(float4*)(pb + (size_t)v*HW) = r;
    }
}

// ---------------- pole fix (rows 0 and H-1 -> longitude mean) ----------------
__global__ void __launch_bounds__(256) k_pole(float* pext, int use_proj) {
    float* base = use_proj ? g_proj : pext;
    int c   = blockIdx.x >> 1;
    int row = (blockIdx.x & 1) ? (Hh - 1) : 0;
    float* rp = base + ((size_t)c*Hh + row)*Ww;

    __shared__ float sh[256];
    float s = 0.0f;
    for (int i = threadIdx.x; i < Ww; i += 256) s += rp[i];
    sh[threadIdx.x] = s;
    __syncthreads();
    for (int o = 128; o > 0; o >>= 1) {
        if (threadIdx.x < o) sh[threadIdx.x] += sh[threadIdx.x + o];
        __syncthreads();
    }
    float m = sh[0] / (float)Ww;
    for (int i = threadIdx.x; i < Ww; i += 256) rp[i] = m;
}

// ---------------- K2: advect (departure + geo-padded bicubic + depthwise) ----------------
// One thread per sample (b,v,h,w) — max TLP (R4 lesson). Instruction diet:
// row-trig table, custom asin/atan2, hoisted divisions, no norm round-trip.
__global__ void __launch_bounds__(256) k_advect(const float* __restrict__ uin,
                                                const float* __restrict__ vin,
                                                const float* __restrict__ lonG,
                                                const float* __restrict__ dww,
                                                const float* __restrict__ dwb) {
    int idx = blockIdx.x*256 + threadIdx.x;
    if (idx >= NSAMP) return;
    int bv = idx / HW;
    int p  = idx - bv*HW;
    int h  = p / Ww;                       // const-div -> umulhi sequence

    float dt       = g_consts[0];
    float min_lat  = g_consts[1];
    float min_lon  = g_consts[2];
    float inv_dlat = g_consts[3];
    float inv_dlon = g_consts[4];
    float slg = g_rowtrig[2*h];
    float clg = g_rowtrig[2*h+1];
    float lon_g = __ldg(&lonG[p]);

    float uu = uin[idx];
    float vv = vin[idx];

    float lon_pr = -uu * dt;
    float lat_pr = -vv * dt;
    float slp, clp, slo, clo;
    __sincosf(lat_pr, &slp, &clp);
    __sincosf(lon_pr, &slo, &clo);

    float sin_lat = slp*clg + clp*clo*slg;
    const float CL = 1.0f - 1e-7f;
    sin_lat = fminf(fmaxf(sin_lat, -CL), CL);
    float lat_dep = asin_fast(sin_lat);

    float num = clp * slo;
    float den = clp*clo*clg - slp*slg;
    const float TWO_PI = 6.28318530717958647692f;
    float lon_dep = lon_g + atan2_fast(num, den) + TWO_PI;   // in (pi, 5*pi)
    if (lon_dep >= TWO_PI) lon_dep -= TWO_PI;
    if (lon_dep >= TWO_PI) lon_dep -= TWO_PI;

    // ix = pix_x + 2 exactly (norm/unnorm round trip is identity in exact math;
    // fp32 deviation ~4e-5 px, far below tolerance)
    float ix = fmaf(lon_dep - min_lon, inv_dlon, 2.0f);
    float iy = fmaf(lat_dep - min_lat, inv_dlat, 2.0f);

    float xf = floorf(ix), yf = floorf(iy);
    float tx = ix - xf,    ty = iy - yf;
    int x0 = (int)xf, y0 = (int)yf;
    x0 = min(max(x0, 1), Ww + 1);     // safety clamp (no-op normally)
    y0 = min(max(y0, 1), Hh + 1);

    const float Aa = -0.75f;
    float t1 = tx + 1.0f, t2 = 1.0f - tx, t3 = 2.0f - tx;
    float wx0 = ((Aa*t1 - 5.0f*Aa)*t1 + 8.0f*Aa)*t1 - 4.0f*Aa;
    float wx1 = ((Aa + 2.0f)*tx - (Aa + 3.0f))*tx*tx + 1.0f;
    float wx2 = ((Aa + 2.0f)*t2 - (Aa + 3.0f))*t2*t2 + 1.0f;
    float wx3 = ((Aa*t3 - 5.0f*Aa)*t3 + 8.0f*Aa)*t3 - 4.0f*Aa;
    float s1 = ty + 1.0f, s2 = 1.0f - ty, s3 = 2.0f - ty;
    float wy0 = ((Aa*s1 - 5.0f*Aa)*s1 + 8.0f*Aa)*s1 - 4.0f*Aa;
    float wy1 = ((Aa + 2.0f)*ty - (Aa + 3.0f))*ty*ty + 1.0f;
    float wy2 = ((Aa + 2.0f)*s2 - (Aa + 3.0f))*s2*s2 + 1.0f;
    float wy3 = ((Aa*s3 - 5.0f*Aa)*s3 + 8.0f*Aa)*s3 - 4.0f*Aa;

    // column indices: cyclic (unshifted) and pole-shifted (+W/2)
    int cbase = x0 - 3;
    int cb0 = cbase;     if (cb0 <  0)  cb0 += Ww; if (cb0 >= Ww) cb0 -= Ww;
    int cb1 = cbase + 1; if (cb1 <  0)  cb1 += Ww; if (cb1 >= Ww) cb1 -= Ww;
    int cb2 = cbase + 2; if (cb2 <  0)  cb2 += Ww; if (cb2 >= Ww) cb2 -= Ww;
    int cb3 = cbase + 3; if (cb3 <  0)  cb3 += Ww; if (cb3 >= Ww) cb3 -= Ww;
    int cs0 = cb0 + Ww/2; if (cs0 >= Ww) cs0 -= Ww;
    int cs1 = cb1 + Ww/2; if (cs1 >= Ww) cs1 -= Ww;
    int cs2 = cb2 + Ww/2; if (cs2 >= Ww) cs2 -= Ww;
    int cs3 = cb3 + Ww/2; if (cs3 >= Ww) cs3 -= Ww;

    const float* pr = g_proj + (size_t)bv*HW;
    float acc = 0.0f;

#define ROWSUM(WYV, DY) do {                                                   \
        int yy = y0 - 1 + (DY);                                                \
        int yi = yy - 2;                                                       \
        int r, shf;                                                            \
        if (yi < 0)        { r = 1 - yy;        shf = 1; }                     \
        else if (yi >= Hh) { r = 2*Hh + 1 - yy; shf = 1; }                     \
        else               { r = yi;            shf = 0; }                     \
        const float* row = pr + (size_t)r*Ww;                                  \
        int c0 = shf ? cs0 : cb0;                                              \
        int c1 = shf ? cs1 : cb1;                                              \
        int c2 = shf ? cs2 : cb2;                                              \
        int c3 = shf ? cs3 : cb3;                                              \
        float s = fmaf(wx3, __ldg(&row[c3]),                                   \
                  fmaf(wx2, __ldg(&row[c2]),                                   \
                  fmaf(wx1, __ldg(&row[c1]), wx0*__ldg(&row[c0]))));           \
        acc = fmaf((WYV), s, acc);                                             \
    } while (0)

    ROWSUM(wy0, 0);
    ROWSUM(wy1, 1);
    ROWSUM(wy2, 2);
    ROWSUM(wy3, 3);
#undef ROWSUM

    int v = bv & (NVc - 1);
    g_y[idx] = acc * __ldg(&dww[v]) + __ldg(&dwb[v]);
}

// ---------------- K3: up projection (g_y[B,16,H,W] -> out[B,128,H,W]) ----------------
// 4 pixels/thread, FFMA2, float4 I/O (R2 config).
__global__ void __launch_bounds__(256) k_up(const float* __restrict__ uw,
                                            const float* __restrict__ ub,
                                            float* __restrict__ out) {
    __shared__ __align__(16) unsigned long long wsh[HIDc*NVc];  // [o][v], (w,w) pairs
    __shared__ float bsh[HIDc];
    int tid = threadIdx.x;
    for (int i = tid; i < HIDc*NVc; i += 256) {
        float w = uw[i];                 // up_w row-major [o][v]
        wsh[i] = pk2(w, w);
    }
    if (tid < HIDc) bsh[tid] = ub[tid];
    __syncthreads();

    int t = blockIdx.x*256 + tid;
    int q0 = t * 4;
    if (q0 >= NPIX) return;
    int b = q0 / HW;
    int p = q0 - b*HW;

    const float* yb = g_y + (size_t)b*NVc*HW + p;
    unsigned long long y0p[NVc], y1p[NVc];
    #pragma unroll
    for (int v = 0; v < NVc; v++) {
        float4 yv = *(const float4*)(yb + (size_t)v*HW);
        y0p[v] = pk2(yv.x, yv.y);
        y1p[v] = pk2(yv.z, yv.w);
    }

    float* ob = out + (size_t)b*HIDc*HW + p;
    #pragma unroll 2
    for (int o = 0; o < HIDc; o++) {
        float bias = bsh[o];
        unsigned long long a0 = pk2(bias, bias);
        unsigned long long a1 = a0;
        const ulonglong2* wr = (const ulonglong2*)&wsh[o*NVc];
        #pragma unroll
        for (int j = 0; j < 8; j++) {
            ulonglong2 ww = wr[j];
            a0 = ffma2(y0p[2*j],   ww.x, a0);
            a1 = ffma2(y1p[2*j],   ww.x, a1);
            a0 = ffma2(y0p[2*j+1], ww.y, a0);
            a1 = ffma2(y1p[2*j+1], ww.y, a1);
        }
        float4 r;
        upk2(a0, r.x, r.y);
        upk2(a1, r.z, r.w);
        *(float4*)(ob + (size_t)o*HW) = r;
    }
}

// ---------------- launcher ----------------
extern "C" void kernel_launch(void* const* d_in, const int* in_sizes, int n_in,
                              void* d_out, int out_size) {
    const float* hidden = (const float*)d_in[0];
    const float* u      = (const float*)d_in[1];
    const float* v      = (const float*)d_in[2];
    const float* dt     = (const float*)d_in[3];
    const float* latg   = (const float*)d_in[4];
    const float* lonG   = (const float*)d_in[5];
    const float* down_w = (const float*)d_in[6];
    const float* down_b = (const float*)d_in[7];
    const float* dw_w   = (const float*)d_in[8];
    const float* dw_b   = (const float*)d_in[9];
    const float* up_w   = (const float*)d_in[10];
    const float* up_b   = (const float*)d_in[11];
    float* out = (float*)d_out;

    int quad_blocks = (NPIX/4 + 255) / 256;                   // 508
    k_prep<<<2, 256>>>(latg, lonG, dt);
    k_down<<<quad_blocks, 256>>>(hidden, down_w, down_b);
    k_pole<<<Bc*NVc*2, 256>>>(nullptr, 1);                    // fix g_proj poles
    k_advect<<<(NSAMP + 255)/256, 256>>>(u, v, lonG, dw_w, dw_b);
    k_up<<<quad_blocks, 256>>>(up_w, up_b, out);
    k_pole<<<Bc*HIDc*2, 256>>>(out, 0);                       // fix output poles
}